// round 9
// baseline (speedup 1.0000x reference)
#include <cuda_runtime.h>
#include <cuda_bf16.h>
#include <math.h>
#include <stdint.h>

// NT-Xent loss: fused bf16 mma.sync GEMM + streaming base-2 softmax.
// R6: ldmatrix fragment loads + 512-thread CTAs (4 warps/SMSP) for latency hiding.

#define NTOT   8192
#define BHALF  4096
#define DK     128
#define TM     128
#define TNJ    128              // cols per j-tile
#define NJT    32               // j-tiles per CTA (4096/128)
#define RS     272              // smem row stride bytes (128 bf16 + 8 pad)
#define SCALE_B2 2.68579530f    // sqrt(log2(e)/0.2)
#define LN2      0.69314718055994531f
#define SKIP_THR 40.0f

__device__ __align__(16) __nv_bfloat16 g_zb[NTOT * DK];
__device__ float g_m[8 * NTOT];   // partials: p = half*4 + wn
__device__ float g_s[8 * NTOT];
__device__ float g_t[8 * NTOT];

// ---------------------------------------------------------------------------
__global__ void prep_kernel(const float* __restrict__ z1,
                            const float* __restrict__ z2) {
    int idx = blockIdx.x * blockDim.x + threadIdx.x;      // float4 index
    const int half4 = BHALF * DK / 4;
    float4 v = (idx < half4) ? ((const float4*)z1)[idx]
                             : ((const float4*)z2)[idx - half4];
    __nv_bfloat162 lo = __floats2bfloat162_rn(v.x * SCALE_B2, v.y * SCALE_B2);
    __nv_bfloat162 hi = __floats2bfloat162_rn(v.z * SCALE_B2, v.w * SCALE_B2);
    __nv_bfloat162* o = (__nv_bfloat162*)&g_zb[idx * 4];
    o[0] = lo; o[1] = hi;
}

// ---------------------------------------------------------------------------
__device__ __forceinline__ float ex2f(float x) {
    float y; asm("ex2.approx.ftz.f32 %0, %1;" : "=f"(y) : "f"(x)); return y;
}
__device__ __forceinline__ uint32_t smem_u32(const void* p) {
    uint32_t a;
    asm("{ .reg .u64 t; cvta.to.shared.u64 t, %1; cvt.u32.u64 %0, t; }"
        : "=r"(a) : "l"(p));
    return a;
}
__device__ __forceinline__ void cp16(uint32_t dst, const void* src) {
    asm volatile("cp.async.cg.shared.global [%0], [%1], 16;"
                 :: "r"(dst), "l"(src) : "memory");
}
__device__ __forceinline__ void ldsm4(uint32_t* r, uint32_t a) {
    asm volatile("ldmatrix.sync.aligned.m8n8.x4.shared.b16 {%0,%1,%2,%3}, [%4];"
                 : "=r"(r[0]), "=r"(r[1]), "=r"(r[2]), "=r"(r[3]) : "r"(a));
}
__device__ __forceinline__ void mma16816(float* c, const uint32_t* a,
                                         uint32_t b0, uint32_t b1) {
    asm volatile(
        "mma.sync.aligned.m16n8k16.row.col.f32.bf16.bf16.f32 "
        "{%0,%1,%2,%3}, {%4,%5,%6,%7}, {%8,%9}, {%0,%1,%2,%3};"
        : "+f"(c[0]), "+f"(c[1]), "+f"(c[2]), "+f"(c[3])
        : "r"(a[0]), "r"(a[1]), "r"(a[2]), "r"(a[3]), "r"(b0), "r"(b1));
}

// ---------------------------------------------------------------------------
// 128 CTAs x 512 threads. CTA b: rows (b>>1)*128, col half (b&1)*4096.
// smem: A tile [128][RS], B double buffer 2x[128][RS].
// 4x4 warp grid: wm = wid&3 (32 rows), wn = wid>>2 (32 cols).
// ---------------------------------------------------------------------------
__global__ __launch_bounds__(512, 1) void ntxent_kernel() {
    extern __shared__ char smc[];
    const uint32_t smb = smem_u32(smc);
    const int tid  = threadIdx.x;
    const int wid  = tid >> 5;
    const int lane = tid & 31;
    const int q = lane & 3, g = lane >> 2;
    const int wm = wid & 3, wn = wid >> 2;          // 4 x 4 warps
    const int i0 = (int)(blockIdx.x >> 1) * TM;
    const int half = blockIdx.x & 1;
    const int jh = half * BHALF;

    const uint32_t sA  = smb;
    const uint32_t sB0 = smb + 128 * RS;
    const uint32_t sB1 = sB0 + 128 * RS;

    // ldmatrix lane-address components (constant per thread)
    const int a_row8  = (lane & 7) + ((lane >> 3) & 1) * 8;   // row within 16
    const int a_kb    = (lane >> 4) * 16;                     // k-half byte offset
    const int b_nrow  = (lane & 7) + (lane >> 4) * 8;         // n within 16
    const int b_kb    = ((lane >> 3) & 1) * 16;

    // Prologue: A tile + B tile 0. 2048 16B chunks each / 512 threads.
    #pragma unroll
    for (int k = 0; k < 4; ++k) {
        int u = tid + k * 512;
        int row = u >> 4, c = u & 15;
        cp16(sA + row * RS + c * 16, &g_zb[(i0 + row) * DK + c * 8]);
    }
    #pragma unroll
    for (int k = 0; k < 4; ++k) {
        int u = tid + k * 512;
        int row = u >> 4, c = u & 15;
        cp16(sB0 + row * RS + c * 16, &g_zb[(jh + row) * DK + c * 8]);
    }
    asm volatile("cp.async.commit_group;" ::: "memory");

    float rm[4], rs[4], tv[4];
    #pragma unroll
    for (int r = 0; r < 4; ++r) { rm[r] = -INFINITY; rs[r] = 0.f; tv[r] = -INFINITY; }

    int rowid[4];
    #pragma unroll
    for (int rr = 0; rr < 4; ++rr)
        rowid[rr] = i0 + wm * 32 + (rr >> 1) * 16 + (rr & 1) * 8 + g;

    const uint32_t aAddrBase = sA + (wm * 32 + a_row8) * RS + a_kb;

    for (int jt = 0; jt < NJT; ++jt) {
        asm volatile("cp.async.wait_group 0;" ::: "memory");
        __syncthreads();

        if (jt + 1 < NJT) {
            uint32_t nb = ((jt + 1) & 1) ? sB1 : sB0;
            int jr0 = jh + (jt + 1) * TNJ;
            #pragma unroll
            for (int k = 0; k < 4; ++k) {
                int u = tid + k * 512;
                int row = u >> 4, c = u & 15;
                cp16(nb + row * RS + c * 16, &g_zb[(jr0 + row) * DK + c * 8]);
            }
            asm volatile("cp.async.commit_group;" ::: "memory");
        }

        const uint32_t bb = (jt & 1) ? sB1 : sB0;
        const uint32_t bAddrBase = bb + (wn * 32 + b_nrow) * RS + b_kb;

        float acc[2][4][4];
        #pragma unroll
        for (int mt = 0; mt < 2; ++mt)
            #pragma unroll
            for (int nt = 0; nt < 4; ++nt)
                #pragma unroll
                for (int c = 0; c < 4; ++c) acc[mt][nt][c] = 0.f;

        #pragma unroll
        for (int ks = 0; ks < 8; ++ks) {
            uint32_t a[2][4], b[2][4];   // b[p] covers nt = 2p, 2p+1
            ldsm4(a[0], aAddrBase + ks * 32);
            ldsm4(a[1], aAddrBase + 16 * RS + ks * 32);
            ldsm4(b[0], bAddrBase + ks * 32);
            ldsm4(b[1], bAddrBase + 16 * RS + ks * 32);
            #pragma unroll
            for (int p = 0; p < 2; ++p) {
                mma16816(acc[0][2 * p],     a[0], b[p][0], b[p][1]);
                mma16816(acc[1][2 * p],     a[1], b[p][0], b[p][1]);
                mma16816(acc[0][2 * p + 1], a[0], b[p][2], b[p][3]);
                mma16816(acc[1][2 * p + 1], a[1], b[p][2], b[p][3]);
            }
        }

        // Fused epilogue: online (m, s) per owned row; rare diag/target fixup.
        int jbase = jh + jt * TNJ + wn * 32;
        #pragma unroll
        for (int rr = 0; rr < 4; ++rr) {
            const int mt = rr >> 1, o = (rr & 1) * 2;
            const int r = rowid[rr];
            float v[8];
            #pragma unroll
            for (int nt = 0; nt < 4; ++nt) {
                v[2 * nt]     = acc[mt][nt][o];
                v[2 * nt + 1] = acc[mt][nt][o + 1];
            }
            int tcol = (r + BHALF) & (NTOT - 1);
            if ((unsigned)(r - jbase) < 32u || (unsigned)(tcol - jbase) < 32u) {
                #pragma unroll
                for (int e = 0; e < 8; ++e) {
                    int j = jbase + (e >> 1) * 8 + 2 * q + (e & 1);
                    if (j == tcol) tv[rr] = v[e];
                    if (j == r)    v[e] = -INFINITY;   // diag mask
                }
            }
            float m0 = fmaxf(v[0], v[1]), m1 = fmaxf(v[2], v[3]);
            float m2 = fmaxf(v[4], v[5]), m3 = fmaxf(v[6], v[7]);
            float mx = fmaxf(fmaxf(m0, m1), fmaxf(m2, m3));
            if (mx > rm[rr] - SKIP_THR) {
                float mn = fmaxf(rm[rr], mx);
                float a0 = rs[rr] * ex2f(rm[rr] - mn);
                float a1 = 0.f, a2 = 0.f, a3 = 0.f;
                a0 += ex2f(v[0] - mn); a1 += ex2f(v[1] - mn);
                a2 += ex2f(v[2] - mn); a3 += ex2f(v[3] - mn);
                a0 += ex2f(v[4] - mn); a1 += ex2f(v[5] - mn);
                a2 += ex2f(v[6] - mn); a3 += ex2f(v[7] - mn);
                rs[rr] = (a0 + a1) + (a2 + a3);
                rm[rr] = mn;
            }
        }
    }

    // Quad reduction (lanes q=0..3 share rows, disjoint cols).
    #pragma unroll
    for (int off = 1; off <= 2; off <<= 1) {
        #pragma unroll
        for (int rr = 0; rr < 4; ++rr) {
            float m2 = __shfl_xor_sync(0xffffffffu, rm[rr], off);
            float s2 = __shfl_xor_sync(0xffffffffu, rs[rr], off);
            float t2 = __shfl_xor_sync(0xffffffffu, tv[rr], off);
            float nm = fmaxf(rm[rr], m2);
            rs[rr] = rs[rr] * ex2f(rm[rr] - nm) + s2 * ex2f(m2 - nm);
            rm[rr] = nm;
            tv[rr] = fmaxf(tv[rr], t2);
        }
    }
    if (q == 0) {
        int p = half * 4 + wn;
        #pragma unroll
        for (int rr = 0; rr < 4; ++rr) {
            int idx = p * NTOT + rowid[rr];
            g_m[idx] = rm[rr];
            g_s[idx] = rs[rr];
            g_t[idx] = tv[rr];
        }
    }
}

// ---------------------------------------------------------------------------
__global__ void combine_kernel(float* __restrict__ out) {
    __shared__ float red[256];
    int tid = threadIdx.x;
    float acc = 0.0f;
    for (int i = tid; i < NTOT; i += 256) {
        float m = -INFINITY, t = -INFINITY;
        #pragma unroll
        for (int p = 0; p < 8; ++p) {
            m = fmaxf(m, g_m[p * NTOT + i]);
            t = fmaxf(t, g_t[p * NTOT + i]);
        }
        float s = 0.0f;
        #pragma unroll
        for (int p = 0; p < 8; ++p)
            s += g_s[p * NTOT + i] * exp2f(g_m[p * NTOT + i] - m);
        acc += (m + log2f(s) - t);
    }
    red[tid] = acc;
    __syncthreads();
    for (int st = 128; st > 0; st >>= 1) {
        if (tid < st) red[tid] += red[tid + st];
        __syncthreads();
    }
    if (tid == 0) out[0] = red[0] * (LN2 / (float)NTOT);
}

// ---------------------------------------------------------------------------
extern "C" void kernel_launch(void* const* d_in, const int* in_sizes, int n_in,
                              void* d_out, int out_size) {
    const float* z1 = (const float*)d_in[0];
    const float* z2 = (const float*)d_in[1];
    float* out = (float*)d_out;

    const int smem_bytes = 3 * 128 * RS;   // 104448 B
    cudaFuncSetAttribute(ntxent_kernel,
                         cudaFuncAttributeMaxDynamicSharedMemorySize, smem_bytes);

    prep_kernel<<<(NTOT * DK / 4) / 256, 256>>>(z1, z2);
    ntxent_kernel<<<NTOT / TM * 2, 512, smem_bytes>>>();
    combine_kernel<<<1, 256>>>(out);
}

// round 10
// speedup vs baseline: 1.0033x; 1.0033x over previous
#include <cuda_runtime.h>
#include <cuda_bf16.h>
#include <math.h>
#include <stdint.h>

// NT-Xent loss, triangular-symmetric fused GEMM+softmax.
// sim = z z^T (symmetric): compute only upper-triangle 128x128 tiles (2080 of
// 4096); each off-diagonal tile updates row-stats for its row-block AND
// col-stats for its col-block. Diag mask (bi==bj) and target capture
// (bj-bi==32) both live on the tile-local diagonal since 4096 % 128 == 0.

#define NTOT   8192
#define NB     64               // 8192 / 128 row blocks
#define BHALF  4096
#define DK     128
#define RS     272              // smem row stride bytes (128 bf16 + 8 pad)
#define TILES_PER_CTA 16
#define GRID_MAIN 130           // 130 * 16 == 2080 == 64*65/2
#define SCALE_B2 2.68579530f    // sqrt(log2(e)/0.2)
#define LN2      0.69314718055994531f
#define SKIP_THR 40.0f

__device__ __align__(16) __nv_bfloat16 g_zb[NTOT * DK];
__device__ float g_pm[NB * NTOT];   // per-row partial max, slot = opposite block
__device__ float g_ps[NB * NTOT];   // per-row partial sum
__device__ float g_t[NTOT];         // target logits
__device__ float g_loss[NTOT];

// ---------------------------------------------------------------------------
__global__ void prep_kernel(const float* __restrict__ z1,
                            const float* __restrict__ z2) {
    int idx = blockIdx.x * blockDim.x + threadIdx.x;      // float4 index
    const int half4 = BHALF * DK / 4;
    float4 v = (idx < half4) ? ((const float4*)z1)[idx]
                             : ((const float4*)z2)[idx - half4];
    __nv_bfloat162 lo = __floats2bfloat162_rn(v.x * SCALE_B2, v.y * SCALE_B2);
    __nv_bfloat162 hi = __floats2bfloat162_rn(v.z * SCALE_B2, v.w * SCALE_B2);
    __nv_bfloat162* o = (__nv_bfloat162*)&g_zb[idx * 4];
    o[0] = lo; o[1] = hi;
}

// ---------------------------------------------------------------------------
__device__ __forceinline__ float ex2f(float x) {
    float y; asm("ex2.approx.ftz.f32 %0, %1;" : "=f"(y) : "f"(x)); return y;
}
__device__ __forceinline__ uint32_t smem_u32(const void* p) {
    uint32_t a;
    asm("{ .reg .u64 t; cvta.to.shared.u64 t, %1; cvt.u32.u64 %0, t; }"
        : "=r"(a) : "l"(p));
    return a;
}
__device__ __forceinline__ void cp16(uint32_t dst, const void* src) {
    asm volatile("cp.async.cg.shared.global [%0], [%1], 16;"
                 :: "r"(dst), "l"(src) : "memory");
}
__device__ __forceinline__ uint32_t lds32(uint32_t a) {
    uint32_t v; asm volatile("ld.shared.b32 %0, [%1];" : "=r"(v) : "r"(a)); return v;
}
__device__ __forceinline__ void mma16816(float* c, const uint32_t* a,
                                         uint32_t b0, uint32_t b1) {
    asm volatile(
        "mma.sync.aligned.m16n8k16.row.col.f32.bf16.bf16.f32 "
        "{%0,%1,%2,%3}, {%4,%5,%6,%7}, {%8,%9}, {%0,%1,%2,%3};"
        : "+f"(c[0]), "+f"(c[1]), "+f"(c[2]), "+f"(c[3])
        : "r"(a[0]), "r"(a[1]), "r"(a[2]), "r"(a[3]), "r"(b0), "r"(b1));
}

// SMEM layout (bytes)
#define SM_A0   0
#define SM_A1   34816
#define SM_B0   69632
#define SM_B1   104448
#define SM_ROWP 139264                     // float [2][128][2]
#define SM_COLP (SM_ROWP + 2048)           // float [4][128][2]
#define SM_TOT  (SM_COLP + 4096)           // 145408

// ---------------------------------------------------------------------------
// 130 CTAs x 256 threads; CTA c processes triangle tiles [16c, 16c+16).
// Warp grid 4x2: wm = wid&3 (32 rows), wn = wid>>2 (64 cols). R5 inner loop.
// ---------------------------------------------------------------------------
__global__ __launch_bounds__(256, 1) void ntxent_tri_kernel() {
    extern __shared__ char smc[];
    const uint32_t smb = smem_u32(smc);
    float* rowP = (float*)(smc + SM_ROWP);
    float* colP = (float*)(smc + SM_COLP);

    const int tid  = threadIdx.x;
    const int wid  = tid >> 5;
    const int lane = tid & 31;
    const int q = lane & 3, g = lane >> 2;
    const int wm = wid & 3, wn = wid >> 2;

    // decode first tile (bi, bj) of this CTA
    int t0 = (int)blockIdx.x * TILES_PER_CTA;
    int cbi = 0, rem = t0;
    while (rem >= NB - cbi) { rem -= NB - cbi; ++cbi; }
    int cbj = cbi + rem;

    // prologue: load tile 0 A,B into buffer 0
    {
        const __nv_bfloat16* za = &g_zb[cbi * 128 * DK];
        const __nv_bfloat16* zb = &g_zb[cbj * 128 * DK];
        #pragma unroll
        for (int k = 0; k < 8; ++k) {
            int u = tid + k * 256;
            int row = u >> 4, c = u & 15;
            cp16(smb + SM_A0 + row * RS + c * 16, za + row * DK + c * 8);
            cp16(smb + SM_B0 + row * RS + c * 16, zb + row * DK + c * 8);
        }
        asm volatile("cp.async.commit_group;" ::: "memory");
    }

    for (int s = 0; s < TILES_PER_CTA; ++s) {
        asm volatile("cp.async.wait_group 0;" ::: "memory");
        __syncthreads();

        // next tile coords + prefetch
        int pbi = cbi, pbj = cbj + 1;
        if (pbj == NB) { ++pbi; pbj = pbi; }
        if (s + 1 < TILES_PER_CTA) {
            uint32_t na = smb + (((s + 1) & 1) ? SM_A1 : SM_A0);
            uint32_t nbuf = smb + (((s + 1) & 1) ? SM_B1 : SM_B0);
            const __nv_bfloat16* za = &g_zb[pbi * 128 * DK];
            const __nv_bfloat16* zb = &g_zb[pbj * 128 * DK];
            #pragma unroll
            for (int k = 0; k < 8; ++k) {
                int u = tid + k * 256;
                int row = u >> 4, c = u & 15;
                cp16(na   + row * RS + c * 16, za + row * DK + c * 8);
                cp16(nbuf + row * RS + c * 16, zb + row * DK + c * 8);
            }
            asm volatile("cp.async.commit_group;" ::: "memory");
        }

        const uint32_t sA = smb + ((s & 1) ? SM_A1 : SM_A0);
        const uint32_t bb = smb + ((s & 1) ? SM_B1 : SM_B0);

        // ---- MMA (verbatim R5 inner loop) ----
        float acc[2][8][4];
        #pragma unroll
        for (int mt = 0; mt < 2; ++mt)
            #pragma unroll
            for (int nt = 0; nt < 8; ++nt)
                #pragma unroll
                for (int c = 0; c < 4; ++c) acc[mt][nt][c] = 0.f;

        #pragma unroll
        for (int ks = 0; ks < 8; ++ks) {
            uint32_t a[2][4];
            #pragma unroll
            for (int mt = 0; mt < 2; ++mt) {
                uint32_t ra = sA + (wm * 32 + mt * 16 + g) * RS + ks * 32 + q * 4;
                a[mt][0] = lds32(ra);
                a[mt][1] = lds32(ra + 8 * RS);
                a[mt][2] = lds32(ra + 16);
                a[mt][3] = lds32(ra + 8 * RS + 16);
            }
            #pragma unroll
            for (int nt = 0; nt < 8; ++nt) {
                uint32_t rb = bb + (wn * 64 + nt * 8 + g) * RS + ks * 32 + q * 4;
                uint32_t b0 = lds32(rb);
                uint32_t b1 = lds32(rb + 16);
                mma16816(acc[0][nt], a[0], b0, b1);
                mma16816(acc[1][nt], a[1], b0, b1);
            }
        }

        const bool isDiag = (cbi == cbj);
        const bool isTgt  = (cbj - cbi == 32);

        // ---- row-side epilogue: tile-local (m,s) for rows of block cbi ----
        #pragma unroll
        for (int rr = 0; rr < 4; ++rr) {
            const int mt = rr >> 1, o = (rr & 1) * 2;
            const int r_loc = wm * 32 + mt * 16 + (rr & 1) * 8 + g;
            float v[16];
            #pragma unroll
            for (int nt = 0; nt < 8; ++nt) {
                v[2 * nt]     = acc[mt][nt][o];
                v[2 * nt + 1] = acc[mt][nt][o + 1];
            }
            if (isDiag || isTgt) {
                // tile-local diagonal element (r_loc, r_loc), single owner
                int lc = r_loc & 63;
                if ((r_loc >> 6) == wn && ((lc >> 1) & 3) == q) {
                    int vi = (lc >> 3) * 2 + (lc & 1);
                    if (isTgt) {
                        float vd = v[vi];
                        g_t[cbi * 128 + r_loc] = vd;   // row i's target
                        g_t[cbj * 128 + r_loc] = vd;   // row i+4096's target
                    } else {
                        v[vi] = -INFINITY;             // diag mask
                    }
                }
            }
            float m0 = fmaxf(v[0], v[1]),   m1 = fmaxf(v[2], v[3]);
            float m2 = fmaxf(v[4], v[5]),   m3 = fmaxf(v[6], v[7]);
            float m4 = fmaxf(v[8], v[9]),   m5 = fmaxf(v[10], v[11]);
            float m6 = fmaxf(v[12], v[13]), m7 = fmaxf(v[14], v[15]);
            float gA = fmaxf(m0, m1), gB = fmaxf(m2, m3);
            float gC = fmaxf(m4, m5), gD = fmaxf(m6, m7);
            float mx = fmaxf(fmaxf(gA, gB), fmaxf(gC, gD));
            float ss = 0.f;
            if (gA > mx - SKIP_THR)
                ss += ex2f(v[0]-mx) + ex2f(v[1]-mx) + ex2f(v[2]-mx) + ex2f(v[3]-mx);
            if (gB > mx - SKIP_THR)
                ss += ex2f(v[4]-mx) + ex2f(v[5]-mx) + ex2f(v[6]-mx) + ex2f(v[7]-mx);
            if (gC > mx - SKIP_THR)
                ss += ex2f(v[8]-mx) + ex2f(v[9]-mx) + ex2f(v[10]-mx) + ex2f(v[11]-mx);
            if (gD > mx - SKIP_THR)
                ss += ex2f(v[12]-mx) + ex2f(v[13]-mx) + ex2f(v[14]-mx) + ex2f(v[15]-mx);
            // quad merge (lanes q=0..3: same rows, disjoint cols)
            #pragma unroll
            for (int off = 1; off <= 2; off <<= 1) {
                float om = __shfl_xor_sync(0xffffffffu, mx, off);
                float os = __shfl_xor_sync(0xffffffffu, ss, off);
                float nm = fmaxf(mx, om);
                ss = ss * ex2f(mx - nm) + os * ex2f(om - nm);
                mx = nm;
            }
            if (q == 0) {
                rowP[(wn * 128 + r_loc) * 2]     = mx;
                rowP[(wn * 128 + r_loc) * 2 + 1] = ss;
            }
        }

        // ---- col-side epilogue: tile-local (m,s) for rows of block cbj ----
        if (!isDiag) {
            #pragma unroll
            for (int nt = 0; nt < 8; ++nt) {
                #pragma unroll
                for (int par = 0; par < 2; ++par) {
                    const int c_loc = wn * 64 + nt * 8 + 2 * q + par;
                    float x0 = acc[0][nt][par],     x1 = acc[0][nt][2 + par];
                    float x2 = acc[1][nt][par],     x3 = acc[1][nt][2 + par];
                    float myMax = fmaxf(fmaxf(x0, x1), fmaxf(x2, x3));
                    float cm = myMax;
                    #pragma unroll
                    for (int off = 4; off <= 16; off <<= 1)
                        cm = fmaxf(cm, __shfl_xor_sync(0xffffffffu, cm, off));
                    float cs = 0.f;
                    if (myMax > cm - SKIP_THR)
                        cs = ex2f(x0-cm) + ex2f(x1-cm) + ex2f(x2-cm) + ex2f(x3-cm);
                    #pragma unroll
                    for (int off = 4; off <= 16; off <<= 1)
                        cs += __shfl_xor_sync(0xffffffffu, cs, off);
                    if (g == 0) {
                        colP[(wm * 128 + c_loc) * 2]     = cm;
                        colP[(wm * 128 + c_loc) * 2 + 1] = cs;
                    }
                }
            }
        }

        __syncthreads();

        // ---- merge partials across warps, write to global slots ----
        if (tid < 128) {
            int row = tid;
            float ma = rowP[row * 2],           sa = rowP[row * 2 + 1];
            float mb = rowP[(128 + row) * 2],   sb = rowP[(128 + row) * 2 + 1];
            float m = fmaxf(ma, mb);
            float ssum = sa * ex2f(ma - m) + sb * ex2f(mb - m);
            g_pm[cbj * NTOT + cbi * 128 + row] = m;
            g_ps[cbj * NTOT + cbi * 128 + row] = ssum;
        } else if (!isDiag) {
            int col = tid - 128;
            float m = colP[col * 2], ssum = colP[col * 2 + 1];
            #pragma unroll
            for (int w = 1; w < 4; ++w) {
                float mp = colP[(w * 128 + col) * 2];
                float sp = colP[(w * 128 + col) * 2 + 1];
                float nm = fmaxf(m, mp);
                ssum = ssum * ex2f(m - nm) + sp * ex2f(mp - nm);
                m = nm;
            }
            g_pm[cbi * NTOT + cbj * 128 + col] = m;
            g_ps[cbi * NTOT + cbj * 128 + col] = ssum;
        }

        cbi = pbi; cbj = pbj;
    }
}

// ---------------------------------------------------------------------------
// Merge the 64 partials per row into per-row loss. grid 32 x 256.
// ---------------------------------------------------------------------------
__global__ void combine_kernel() {
    int i = blockIdx.x * 256 + threadIdx.x;   // 0..8191
    float m = -INFINITY, s = 0.f;
    #pragma unroll 4
    for (int p = 0; p < NB; ++p) {
        float mp = g_pm[p * NTOT + i];
        float sp = g_ps[p * NTOT + i];
        float nm = fmaxf(m, mp);
        s = s * ex2f(m - nm) + sp * ex2f(mp - nm);
        m = nm;
    }
    g_loss[i] = m + __log2f(s) - g_t[i];
}

// ---------------------------------------------------------------------------
__global__ void reduce_kernel(float* __restrict__ out) {
    __shared__ float red[256];
    int tid = threadIdx.x;
    float acc = 0.0f;
    for (int i = tid; i < NTOT; i += 256) acc += g_loss[i];
    red[tid] = acc;
    __syncthreads();
    for (int st = 128; st > 0; st >>= 1) {
        if (tid < st) red[tid] += red[tid + st];
        __syncthreads();
    }
    if (tid == 0) out[0] = red[0] * (LN2 / (float)NTOT);
}

// ---------------------------------------------------------------------------
extern "C" void kernel_launch(void* const* d_in, const int* in_sizes, int n_in,
                              void* d_out, int out_size) {
    const float* z1 = (const float*)d_in[0];
    const float* z2 = (const float*)d_in[1];
    float* out = (float*)d_out;

    cudaFuncSetAttribute(ntxent_tri_kernel,
                         cudaFuncAttributeMaxDynamicSharedMemorySize, SM_TOT);

    prep_kernel<<<(NTOT * DK / 4) / 256, 256>>>(z1, z2);
    ntxent_tri_kernel<<<GRID_MAIN, 256, SM_TOT>>>();
    combine_kernel<<<NTOT / 256, 256>>>();
    reduce_kernel<<<1, 256>>>(out);
}